// round 10
// baseline (speedup 1.0000x reference)
#include <cuda_runtime.h>
#include <cstdint>

#define T_SEQ 2048
#define BATCH 256
#define HID   64
#define INP   7
#define XSTEPS 64                    // steps per prefetch block
#define XBLK_FLOATS (XSTEPS * INP)   // 448 floats per block in GMEM

typedef unsigned long long ull;

__device__ __forceinline__ ull fma2(ull a, ull b, ull c) {
    ull d;
    asm("fma.rn.f32x2 %0, %1, %2, %3;" : "=l"(d) : "l"(a), "l"(b), "l"(c));
    return d;
}
__device__ __forceinline__ ull add2(ull a, ull b) {
    ull d;
    asm("add.rn.f32x2 %0, %1, %2;" : "=l"(d) : "l"(a), "l"(b));
    return d;
}
__device__ __forceinline__ ull pack2(float lo, float hi) {
    ull d; asm("mov.b64 %0, {%1, %2};" : "=l"(d) : "f"(lo), "f"(hi)); return d;
}
__device__ __forceinline__ float2 unpack2(ull a) {
    float2 r; asm("mov.b64 {%0, %1}, %2;" : "=f"(r.x), "=f"(r.y) : "l"(a)); return r;
}
__device__ __forceinline__ float htanh(float x) {
    float y; asm("tanh.approx.f32 %0, %1;" : "=f"(y) : "f"(x)); return y;
}
__device__ __forceinline__ void cpa4(uint32_t dst_smem, const float* src) {
    asm volatile("cp.async.ca.shared.global [%0], [%1], 4;" :: "r"(dst_smem), "l"(src));
}
__device__ __forceinline__ void cp_commit() {
    asm volatile("cp.async.commit_group;" ::: "memory");
}
__device__ __forceinline__ void cp_wait0() {
    asm volatile("cp.async.wait_group 0;" ::: "memory");
}

// grid = 256 CTAs x 128 threads, ONE batch chain per CTA,
// __launch_bounds__(128, 2): two INDEPENDENT CTAs co-resident per SM.
// Separate CTAs have separate barriers, so when one CTA's warps stall at
// bar.sync / in the serial tail, the other CTA's warps issue FMAs — the
// mutual hiding that same-CTA chain pairs (R5/R7) never achieved.
//
// Thread w in [0,128): p = w&1 (gate pair), u = w>>1 (hidden unit),
//   rowA = p*64+u (i/f), rowB = rowA+128 (g/o); weights in registers.
// Per step: z = xz + W_hh·h (16 LDS.128 h-broadcast feeding 64 FMA2),
// unified activations via MUFU.TANH (3 MUFU/warp), gate exchange via
// shfl_xor(1), p==0 lanes update c and store h (double-buffered).
// A compiler barrier between the h-store and the xz tail-shadow keeps the
// STS ahead of bar.sync so the barrier's store-drain is covered by the
// independent xz work. ONE __syncthreads per step.
// x streamed via cp.async double-buffered 64-step ring (8-float padded).
//
// Backward direction = ONE LSTM step on x[T-1] from zero state (scan[0] of
// the reversed sequence), fused as an epilogue with the final linear.
struct Smem {
    float h[2][64];             // double-buffered hidden state
    float hb[64];               // backward h (epilogue)
    float xring[2][XSTEPS * 8]; // padded x ring, 2 blocks
};

__global__ void __launch_bounds__(128, 2)
bilstm_kernel(const float* __restrict__ x,      // [B,T,I]
              const float* __restrict__ Wih_f,  // [256,7]
              const float* __restrict__ Whh_f,  // [256,64]
              const float* __restrict__ bih_f,  // [256]
              const float* __restrict__ bhh_f,  // [256]
              const float* __restrict__ Wih_b,  // [256,7]
              const float* __restrict__ Whh_b,  // unused (h0 = 0 for single bwd step)
              const float* __restrict__ bih_b,  // [256]
              const float* __restrict__ bhh_b,  // [256]
              const float* __restrict__ Wlin,   // [3,128]
              const float* __restrict__ blin,   // [3]
              float* __restrict__ out)          // [B,3]
{
    __shared__ __align__(16) Smem S;

    const int w  = threadIdx.x;
    const int p  = w & 1;            // gate pair selector
    const int u  = w >> 1;           // hidden unit
    const int rA = p * 64 + u;       // gate i (p=0) / f (p=1)
    const int rB = rA + 128;         // gate g (p=0) / o (p=1)
    const int b  = blockIdx.x;

    const float* xb = x + (size_t)b * T_SEQ * INP;

    const uint32_t ring0 = (uint32_t)__cvta_generic_to_shared(&S.xring[0][0]);
    const uint32_t ring1 = (uint32_t)__cvta_generic_to_shared(&S.xring[1][0]);

    // ring fill: 128 threads x 4 padded elements = 512 slots per block
    const int e0 = 4 * w;

    // activation of row B: tanh for p=0 (gate g), sigmoid for p=1 (gate o)
    const float actB_s = (p == 0) ? 1.0f : 0.5f;
    const float actB_m = (p == 0) ? 1.0f : 0.5f;
    const float actB_b = (p == 0) ? 0.0f : 0.5f;

    // ---- weights into registers: 2 rows x 32 f32x2 ----
    ull wA[32], wB[32];
    {
        const ull* a  = reinterpret_cast<const ull*>(Whh_f + rA * HID);
        const ull* c2 = reinterpret_cast<const ull*>(Whh_f + rB * HID);
#pragma unroll
        for (int m = 0; m < 32; m++) wA[m] = a[m];
#pragma unroll
        for (int m = 0; m < 32; m++) wB[m] = c2[m];
    }
    ull wihA[4], wihB[4];
    {
        float t[8];
#pragma unroll
        for (int i = 0; i < INP; i++) t[i] = Wih_f[rA * INP + i];
        t[7] = 0.0f;
#pragma unroll
        for (int m = 0; m < 4; m++) wihA[m] = pack2(t[2 * m], t[2 * m + 1]);
#pragma unroll
        for (int i = 0; i < INP; i++) t[i] = Wih_f[rB * INP + i];
        t[7] = 0.0f;
#pragma unroll
        for (int m = 0; m < 4; m++) wihB[m] = pack2(t[2 * m], t[2 * m + 1]);
    }
    const ull biasA2 = pack2(bih_f[rA] + bhh_f[rA], 0.0f);
    const ull biasB2 = pack2(bih_f[rB] + bhh_f[rB], 0.0f);

    // ---- init: h=0, zero ring pads, prefetch blocks 0 and 1 ----
    if (w < 64) S.h[0][w] = 0.0f;
    {   // zero the j==7 pad slot of all 128 ring rows (2 bufs x 64 slots)
        int bufi = w >> 6, s = w & 63;
        S.xring[bufi][s * 8 + 7] = 0.0f;
        S.xring[bufi ^ 1][s * 8 + 7] = 0.0f;
    }
#pragma unroll
    for (int k = 0; k < 4; k++) {
        int e = e0 + k, s = e >> 3, j = e & 7;
        if (j < INP) cpa4(ring0 + (uint32_t)e * 4, xb + s * INP + j);
    }
    cp_commit();
#pragma unroll
    for (int k = 0; k < 4; k++) {
        int e = e0 + k, s = e >> 3, j = e & 7;
        if (j < INP) cpa4(ring1 + (uint32_t)e * 4, xb + XBLK_FLOATS + s * INP + j);
    }
    cp_commit();
    cp_wait0();
    float c = 0.0f;
    __syncthreads();

    // xz accumulators (h-independent part + bias) for t=0
    ull xzA0, xzA1, xzB0, xzB1;
    const float* xnext;
    {
        ulonglong2 xv = *reinterpret_cast<const ulonglong2*>(&S.xring[0][0]);
        ulonglong2 xw = *reinterpret_cast<const ulonglong2*>(&S.xring[0][4]);
        xzA0 = fma2(wihA[0], xv.x, biasA2);
        xzA1 = fma2(wihA[1], xv.y, 0ull);
        xzB0 = fma2(wihB[0], xv.x, biasB2);
        xzB1 = fma2(wihB[1], xv.y, 0ull);
        xzA0 = fma2(wihA[2], xw.x, xzA0);
        xzA1 = fma2(wihA[3], xw.y, xzA1);
        xzB0 = fma2(wihB[2], xw.x, xzB0);
        xzB1 = fma2(wihB[3], xw.y, xzB1);
        xnext = &S.xring[0][8];
    }

    for (int t = 0; t < T_SEQ; t++) {
        if ((t & (XSTEPS - 1)) == 0 && t) {
            cp_wait0();   // block issued 64 steps ago has landed
            __syncthreads();
            int nb = (t >> 6) + 1;
            if (nb < T_SEQ / XSTEPS) {
                uint32_t dst = (nb & 1) ? ring1 : ring0;
                const float* src = xb + (size_t)nb * XBLK_FLOATS;
#pragma unroll
                for (int k = 0; k < 4; k++) {
                    int e = e0 + k, s = e >> 3, j = e & 7;
                    if (j < INP) cpa4(dst + (uint32_t)e * 4, src + s * INP + j);
                }
            }
            cp_commit();
            // xz for THIS boundary step from the just-waited buffer
            const float* xc = &S.xring[(t >> 6) & 1][0];
            ulonglong2 xv = *reinterpret_cast<const ulonglong2*>(xc);
            ulonglong2 xw = *reinterpret_cast<const ulonglong2*>(xc + 4);
            xzA0 = fma2(wihA[0], xv.x, biasA2);
            xzA1 = fma2(wihA[1], xv.y, 0ull);
            xzB0 = fma2(wihB[0], xv.x, biasB2);
            xzB1 = fma2(wihB[1], xv.y, 0ull);
            xzA0 = fma2(wihA[2], xw.x, xzA0);
            xzA1 = fma2(wihA[3], xw.y, xzA1);
            xzB0 = fma2(wihB[2], xw.x, xzB0);
            xzB1 = fma2(wihB[3], xw.y, xzB1);
            xnext = xc + 8;
        }

        // z = xz + W_hh·h (4 independent accumulator chains)
        ull a0 = xzA0, a1 = xzA1;
        ull b0 = xzB0, b1 = xzB1;
        const ulonglong2* h2 = reinterpret_cast<const ulonglong2*>(S.h[t & 1]);
#pragma unroll
        for (int m = 0; m < 8; m++) {
            ulonglong2 ha  = h2[2 * m];
            ulonglong2 hbv = h2[2 * m + 1];
            a0 = fma2(wA[4 * m + 0], ha.x,  a0);
            a1 = fma2(wA[4 * m + 1], ha.y,  a1);
            b0 = fma2(wB[4 * m + 0], ha.x,  b0);
            b1 = fma2(wB[4 * m + 1], ha.y,  b1);
            a0 = fma2(wA[4 * m + 2], hbv.x, a0);
            a1 = fma2(wA[4 * m + 3], hbv.y, a1);
            b0 = fma2(wB[4 * m + 2], hbv.x, b0);
            b1 = fma2(wB[4 * m + 3], hbv.y, b1);
        }
        float2 fa = unpack2(add2(a0, a1));
        float2 fb = unpack2(add2(b0, b1));
        float zA = fa.x + fa.y;
        float zB = fb.x + fb.y;

        // activations: row A sigmoid (i or f); row B tanh (g) / sigmoid (o)
        float aA = fmaf(0.5f, htanh(0.5f * zA), 0.5f);
        float aB = fmaf(actB_m, htanh(actB_s * zB), actB_b);

        // exchange within lane pair: p=0 holds (i,g); gets (f,o) from p=1
        float oA = __shfl_xor_sync(0xFFFFFFFFu, aA, 1);
        float oB = __shfl_xor_sync(0xFFFFFFFFu, aB, 1);
        if (p == 0) {
            c = oA * c + aA * aB;                 // c = f*c + i*g
            S.h[(t & 1) ^ 1][u] = oB * htanh(c);  // h = o*tanh(c)
        }
        // compiler barrier: keep the h-store issued BEFORE the xz shadow so
        // the STS drains during the shadow, not inside bar.sync
        asm volatile("" ::: "memory");

        // tail shadow: xz for t+1 (non-boundary successors)
        if (((t + 1) & (XSTEPS - 1)) != 0 && t + 1 < T_SEQ) {
            ulonglong2 xv = *reinterpret_cast<const ulonglong2*>(xnext);
            ulonglong2 xw = *reinterpret_cast<const ulonglong2*>(xnext + 4);
            xzA0 = fma2(wihA[0], xv.x, biasA2);
            xzA1 = fma2(wihA[1], xv.y, 0ull);
            xzB0 = fma2(wihB[0], xv.x, biasB2);
            xzB1 = fma2(wihB[1], xv.y, 0ull);
            xzA0 = fma2(wihA[2], xw.x, xzA0);
            xzA1 = fma2(wihA[3], xw.y, xzA1);
            xzB0 = fma2(wihB[2], xw.x, xzB0);
            xzB1 = fma2(wihB[3], xw.y, xzB1);
            xnext += 8;
        }
        __syncthreads();
    }

    // ---- backward direction: ONE step on x[T-1] from zero state ----
    {
        const float* xl = &S.xring[1][63 * 8];   // t=2047 -> buf 1, slot 63
        float zbA = bih_b[rA] + bhh_b[rA];
        float zbB = bih_b[rB] + bhh_b[rB];
#pragma unroll
        for (int i = 0; i < INP; i++) {
            zbA += Wih_b[rA * INP + i] * xl[i];
            zbB += Wih_b[rB * INP + i] * xl[i];
        }
        float aA = fmaf(0.5f, htanh(0.5f * zbA), 0.5f);
        float aB = fmaf(actB_m, htanh(actB_s * zbB), actB_b);
        float oB = __shfl_xor_sync(0xFFFFFFFFu, aB, 1);   // o
        if (p == 0) {
            S.hb[u] = oB * htanh(aA * aB);       // f*c0 == 0
        }
        __syncthreads();
    }

    // ---- final linear: out[b] = W_lin @ concat(h_f, h_b) + b_lin ----
    // final forward h is in S.h[0] (t=2047 writes buffer (2047&1)^1 = 0)
    if (w < 3) {
        float a = blin[w];
#pragma unroll 16
        for (int k = 0; k < 64; k++) a += Wlin[w * 128 + k] * S.h[0][k];
#pragma unroll 16
        for (int k = 0; k < 64; k++) a += Wlin[w * 128 + 64 + k] * S.hb[k];
        out[b * 3 + w] = a;
    }
}

extern "C" void kernel_launch(void* const* d_in, const int* in_sizes, int n_in,
                              void* d_out, int out_size) {
    (void)in_sizes; (void)n_in; (void)out_size;
    bilstm_kernel<<<BATCH, 128>>>(
        (const float*)d_in[0],  (const float*)d_in[1], (const float*)d_in[2],
        (const float*)d_in[3],  (const float*)d_in[4], (const float*)d_in[5],
        (const float*)d_in[6],  (const float*)d_in[7], (const float*)d_in[8],
        (const float*)d_in[9],  (const float*)d_in[10], (float*)d_out);
}

// round 11
// speedup vs baseline: 1.4806x; 1.4806x over previous
#include <cuda_runtime.h>
#include <cstdint>

#define T_SEQ 2048
#define BATCH 256
#define HID   64
#define INP   7
#define XSTEPS 64                    // steps per prefetch block
#define XBLK_FLOATS (XSTEPS * INP)   // 448 floats per block in GMEM
#define NBLK (T_SEQ / XSTEPS)        // 32

typedef unsigned long long ull;

__device__ __forceinline__ ull fma2(ull a, ull b, ull c) {
    ull d;
    asm("fma.rn.f32x2 %0, %1, %2, %3;" : "=l"(d) : "l"(a), "l"(b), "l"(c));
    return d;
}
__device__ __forceinline__ ull add2(ull a, ull b) {
    ull d;
    asm("add.rn.f32x2 %0, %1, %2;" : "=l"(d) : "l"(a), "l"(b));
    return d;
}
__device__ __forceinline__ ull pack2(float lo, float hi) {
    ull d; asm("mov.b64 %0, {%1, %2};" : "=l"(d) : "f"(lo), "f"(hi)); return d;
}
__device__ __forceinline__ float2 unpack2(ull a) {
    float2 r; asm("mov.b64 {%0, %1}, %2;" : "=f"(r.x), "=f"(r.y) : "l"(a)); return r;
}
__device__ __forceinline__ float htanh(float x) {
    float y; asm("tanh.approx.f32 %0, %1;" : "=f"(y) : "f"(x)); return y;
}
__device__ __forceinline__ void cpa4(uint32_t dst_smem, const float* src) {
    asm volatile("cp.async.ca.shared.global [%0], [%1], 4;" :: "r"(dst_smem), "l"(src));
}
__device__ __forceinline__ void cp_commit() {
    asm volatile("cp.async.commit_group;" ::: "memory");
}
__device__ __forceinline__ void cp_wait0() {
    asm volatile("cp.async.wait_group 0;" ::: "memory");
}

// grid = 128 CTAs x 128 threads, 1 CTA/SM; each CTA runs TWO batch chains in
// a single instruction stream (weights identical across batch -> register
// weights shared). KEY CHANGE vs R9: the two batches are processed
// SEQUENTIALLY within a step (b0 z-block, b0 tail, b1 z-block, b1 tail) so
// batch0's serial tail (MUFU.TANH / SHFL / c-update) issues UNDER batch1's
// 128-cycle FMA block instead of serializing after it. Only batch1's tail
// remains exposed. Nested loops (32 blocks x 64 steps) remove per-step
// boundary branches; the xz tail-shadow is unconditional (the block-edge
// shadow reads padded garbage that the boundary recompute overwrites).
//
// Thread w in [0,128): p = w&1 (gate pair), u = w>>1 (hidden unit),
//   rowA = p*64+u (i/f), rowB = rowA+128 (g/o).
// Gate exchange = shfl_xor(1); p==0 lanes update c and store h
// (double-buffered per batch). x streamed via cp.async double-buffered
// 64-step rings (8-float padded rows), one per batch.
//
// Backward direction = ONE LSTM step on x[T-1] from zero state (scan[0] of
// the reversed sequence), fused as an epilogue with the final linear.
struct Smem {
    float h[2][2][64];             // [batch][buf][unit]
    float hb[2][64];               // backward h per batch (epilogue)
    float xring[2][2][XSTEPS * 8]; // [batch][buf][slot*8 padded]
    float pad[8];                  // absorbs block-edge shadow over-read
};

__global__ void __launch_bounds__(128, 1)
bilstm_kernel(const float* __restrict__ x,      // [B,T,I]
              const float* __restrict__ Wih_f,  // [256,7]
              const float* __restrict__ Whh_f,  // [256,64]
              const float* __restrict__ bih_f,  // [256]
              const float* __restrict__ bhh_f,  // [256]
              const float* __restrict__ Wih_b,  // [256,7]
              const float* __restrict__ Whh_b,  // unused (h0 = 0 for single bwd step)
              const float* __restrict__ bih_b,  // [256]
              const float* __restrict__ bhh_b,  // [256]
              const float* __restrict__ Wlin,   // [3,128]
              const float* __restrict__ blin,   // [3]
              float* __restrict__ out)          // [B,3]
{
    __shared__ __align__(16) Smem S;

    const int w  = threadIdx.x;
    const int p  = w & 1;            // gate pair selector
    const int u  = w >> 1;           // hidden unit
    const int rA = p * 64 + u;       // gate i (p=0) / f (p=1)
    const int rB = rA + 128;         // gate g (p=0) / o (p=1)
    const int b0 = blockIdx.x * 2;

    const float* xb0 = x + (size_t)b0 * T_SEQ * INP;
    const float* xb1 = x + (size_t)(b0 + 1) * T_SEQ * INP;

    // ring-fill role: thread fills slot (w&63) of batch (w>>6)
    const int tb   = w >> 6;
    const int slot = w & 63;
    const float* xbt = tb ? xb1 : xb0;
    const uint32_t ringt0 = (uint32_t)__cvta_generic_to_shared(&S.xring[tb][0][0]);
    const uint32_t ringt1 = (uint32_t)__cvta_generic_to_shared(&S.xring[tb][1][0]);

    // activation of row B: tanh for p=0 (gate g), sigmoid for p=1 (gate o)
    const float actB_s = (p == 0) ? 1.0f : 0.5f;
    const float actB_m = (p == 0) ? 1.0f : 0.5f;
    const float actB_b = (p == 0) ? 0.0f : 0.5f;

    // ---- weights into registers: 2 rows x 32 f32x2 (shared across batches) ----
    ull wA[32], wB[32];
    {
        const ull* a  = reinterpret_cast<const ull*>(Whh_f + rA * HID);
        const ull* c2 = reinterpret_cast<const ull*>(Whh_f + rB * HID);
#pragma unroll
        for (int m = 0; m < 32; m++) wA[m] = a[m];
#pragma unroll
        for (int m = 0; m < 32; m++) wB[m] = c2[m];
    }
    ull wihA[4], wihB[4];
    {
        float t[8];
#pragma unroll
        for (int i = 0; i < INP; i++) t[i] = Wih_f[rA * INP + i];
        t[7] = 0.0f;
#pragma unroll
        for (int m = 0; m < 4; m++) wihA[m] = pack2(t[2 * m], t[2 * m + 1]);
#pragma unroll
        for (int i = 0; i < INP; i++) t[i] = Wih_f[rB * INP + i];
        t[7] = 0.0f;
#pragma unroll
        for (int m = 0; m < 4; m++) wihB[m] = pack2(t[2 * m], t[2 * m + 1]);
    }
    const ull biasA2 = pack2(bih_f[rA] + bhh_f[rA], 0.0f);
    const ull biasB2 = pack2(bih_f[rB] + bhh_f[rB], 0.0f);

    // ---- init: h=0 (both batches), zero ring pads, prefetch blocks 0,1 ----
    if (w < 64) { S.h[0][0][w] = 0.0f; S.h[1][0][w] = 0.0f; }
    S.xring[tb][0][slot * 8 + 7] = 0.0f;
    S.xring[tb][1][slot * 8 + 7] = 0.0f;
#pragma unroll
    for (int k = 0; k < 7; k++)
        cpa4(ringt0 + (uint32_t)(slot * 8 + k) * 4, xbt + slot * INP + k);
    cp_commit();
#pragma unroll
    for (int k = 0; k < 7; k++)
        cpa4(ringt1 + (uint32_t)(slot * 8 + k) * 4, xbt + XBLK_FLOATS + slot * INP + k);
    cp_commit();
    cp_wait0();
    float c0 = 0.0f, c1 = 0.0f;
    __syncthreads();

    // xz accumulators per batch for t=0
    ull xA0_0, xA1_0, xB0_0, xB1_0;   // batch0
    ull xA0_1, xA1_1, xB0_1, xB1_1;   // batch1
    const float* xnext0 = &S.xring[0][0][0];
    const float* xnext1 = &S.xring[1][0][0];
    {
        ulonglong2 xv = *reinterpret_cast<const ulonglong2*>(xnext0);
        ulonglong2 xw = *reinterpret_cast<const ulonglong2*>(xnext0 + 4);
        xA0_0 = fma2(wihA[0], xv.x, biasA2);
        xA1_0 = fma2(wihA[1], xv.y, 0ull);
        xB0_0 = fma2(wihB[0], xv.x, biasB2);
        xB1_0 = fma2(wihB[1], xv.y, 0ull);
        xA0_0 = fma2(wihA[2], xw.x, xA0_0);
        xA1_0 = fma2(wihA[3], xw.y, xA1_0);
        xB0_0 = fma2(wihB[2], xw.x, xB0_0);
        xB1_0 = fma2(wihB[3], xw.y, xB1_0);
        ulonglong2 yv = *reinterpret_cast<const ulonglong2*>(xnext1);
        ulonglong2 yw = *reinterpret_cast<const ulonglong2*>(xnext1 + 4);
        xA0_1 = fma2(wihA[0], yv.x, biasA2);
        xA1_1 = fma2(wihA[1], yv.y, 0ull);
        xB0_1 = fma2(wihB[0], yv.x, biasB2);
        xB1_1 = fma2(wihB[1], yv.y, 0ull);
        xA0_1 = fma2(wihA[2], yw.x, xA0_1);
        xA1_1 = fma2(wihA[3], yw.y, xA1_1);
        xB0_1 = fma2(wihB[2], yw.x, xB0_1);
        xB1_1 = fma2(wihB[3], yw.y, xB1_1);
        xnext0 += 8;
        xnext1 += 8;
    }

    for (int blk = 0; blk < NBLK; blk++) {
        if (blk) {
            cp_wait0();   // ring block committed at previous boundary landed
            __syncthreads();
            int nb = blk + 1;
            if (nb < NBLK) {
                uint32_t dst = (nb & 1) ? ringt1 : ringt0;
                const float* src = xbt + (size_t)nb * XBLK_FLOATS + slot * INP;
#pragma unroll
                for (int k = 0; k < 7; k++)
                    cpa4(dst + (uint32_t)(slot * 8 + k) * 4, src + k);
            }
            cp_commit();
            // xz for the first step of THIS block from the just-waited buffer
            const float* xc0 = &S.xring[0][blk & 1][0];
            const float* xc1 = &S.xring[1][blk & 1][0];
            ulonglong2 xv = *reinterpret_cast<const ulonglong2*>(xc0);
            ulonglong2 xw = *reinterpret_cast<const ulonglong2*>(xc0 + 4);
            xA0_0 = fma2(wihA[0], xv.x, biasA2);
            xA1_0 = fma2(wihA[1], xv.y, 0ull);
            xB0_0 = fma2(wihB[0], xv.x, biasB2);
            xB1_0 = fma2(wihB[1], xv.y, 0ull);
            xA0_0 = fma2(wihA[2], xw.x, xA0_0);
            xA1_0 = fma2(wihA[3], xw.y, xA1_0);
            xB0_0 = fma2(wihB[2], xw.x, xB0_0);
            xB1_0 = fma2(wihB[3], xw.y, xB1_0);
            ulonglong2 yv = *reinterpret_cast<const ulonglong2*>(xc1);
            ulonglong2 yw = *reinterpret_cast<const ulonglong2*>(xc1 + 4);
            xA0_1 = fma2(wihA[0], yv.x, biasA2);
            xA1_1 = fma2(wihA[1], yv.y, 0ull);
            xB0_1 = fma2(wihB[0], yv.x, biasB2);
            xB1_1 = fma2(wihB[1], yv.y, 0ull);
            xA0_1 = fma2(wihA[2], yw.x, xA0_1);
            xA1_1 = fma2(wihA[3], yw.y, xA1_1);
            xB0_1 = fma2(wihB[2], yw.x, xB0_1);
            xB1_1 = fma2(wihB[3], yw.y, xB1_1);
            xnext0 = xc0 + 8;
            xnext1 = xc1 + 8;
        }

#pragma unroll 2
        for (int i = 0; i < XSTEPS; i++) {
            const int par = i & 1;        // h buffer parity (XSTEPS even)

            // ---------- batch 0: z-block then tail ----------
            ull a0 = xA0_0, a1 = xA1_0, q0 = xB0_0, q1 = xB1_0;
            {
                const ulonglong2* h2 = reinterpret_cast<const ulonglong2*>(S.h[0][par]);
#pragma unroll
                for (int m = 0; m < 8; m++) {
                    ulonglong2 ha  = h2[2 * m];
                    ulonglong2 hbv = h2[2 * m + 1];
                    a0 = fma2(wA[4 * m + 0], ha.x,  a0);
                    a1 = fma2(wA[4 * m + 1], ha.y,  a1);
                    q0 = fma2(wB[4 * m + 0], ha.x,  q0);
                    q1 = fma2(wB[4 * m + 1], ha.y,  q1);
                    a0 = fma2(wA[4 * m + 2], hbv.x, a0);
                    a1 = fma2(wA[4 * m + 3], hbv.y, a1);
                    q0 = fma2(wB[4 * m + 2], hbv.x, q0);
                    q1 = fma2(wB[4 * m + 3], hbv.y, q1);
                }
            }
            {
                float2 fa = unpack2(add2(a0, a1));
                float2 fb = unpack2(add2(q0, q1));
                float zA = fa.x + fa.y;
                float zB = fb.x + fb.y;
                float aA = fmaf(0.5f, htanh(0.5f * zA), 0.5f);
                float aB = fmaf(actB_m, htanh(actB_s * zB), actB_b);
                float oA = __shfl_xor_sync(0xFFFFFFFFu, aA, 1);
                float oB = __shfl_xor_sync(0xFFFFFFFFu, aB, 1);
                if (p == 0) {
                    c0 = oA * c0 + aA * aB;
                    S.h[0][par ^ 1][u] = oB * htanh(c0);
                }
            }

            // ---------- batch 1: z-block (hides batch0 tail) then tail ----------
            ull e0 = xA0_1, e1 = xA1_1, g0 = xB0_1, g1 = xB1_1;
            {
                const ulonglong2* h2 = reinterpret_cast<const ulonglong2*>(S.h[1][par]);
#pragma unroll
                for (int m = 0; m < 8; m++) {
                    ulonglong2 ha  = h2[2 * m];
                    ulonglong2 hbv = h2[2 * m + 1];
                    e0 = fma2(wA[4 * m + 0], ha.x,  e0);
                    e1 = fma2(wA[4 * m + 1], ha.y,  e1);
                    g0 = fma2(wB[4 * m + 0], ha.x,  g0);
                    g1 = fma2(wB[4 * m + 1], ha.y,  g1);
                    e0 = fma2(wA[4 * m + 2], hbv.x, e0);
                    e1 = fma2(wA[4 * m + 3], hbv.y, e1);
                    g0 = fma2(wB[4 * m + 2], hbv.x, g0);
                    g1 = fma2(wB[4 * m + 3], hbv.y, g1);
                }
            }
            {
                float2 fa = unpack2(add2(e0, e1));
                float2 fb = unpack2(add2(g0, g1));
                float zA = fa.x + fa.y;
                float zB = fb.x + fb.y;
                float aA = fmaf(0.5f, htanh(0.5f * zA), 0.5f);
                float aB = fmaf(actB_m, htanh(actB_s * zB), actB_b);
                float oA = __shfl_xor_sync(0xFFFFFFFFu, aA, 1);
                float oB = __shfl_xor_sync(0xFFFFFFFFu, aB, 1);
                if (p == 0) {
                    c1 = oA * c1 + aA * aB;
                    S.h[1][par ^ 1][u] = oB * htanh(c1);
                }
            }

            // ---------- xz shadow for the next step (unconditional) ----------
            // At i==63 this reads past the slot array (padded); the block
            // boundary recomputes xz, so the garbage is never consumed.
            {
                ulonglong2 xv = *reinterpret_cast<const ulonglong2*>(xnext0);
                ulonglong2 xw = *reinterpret_cast<const ulonglong2*>(xnext0 + 4);
                xA0_0 = fma2(wihA[0], xv.x, biasA2);
                xA1_0 = fma2(wihA[1], xv.y, 0ull);
                xB0_0 = fma2(wihB[0], xv.x, biasB2);
                xB1_0 = fma2(wihB[1], xv.y, 0ull);
                xA0_0 = fma2(wihA[2], xw.x, xA0_0);
                xA1_0 = fma2(wihA[3], xw.y, xA1_0);
                xB0_0 = fma2(wihB[2], xw.x, xB0_0);
                xB1_0 = fma2(wihB[3], xw.y, xB1_0);
                ulonglong2 yv = *reinterpret_cast<const ulonglong2*>(xnext1);
                ulonglong2 yw = *reinterpret_cast<const ulonglong2*>(xnext1 + 4);
                xA0_1 = fma2(wihA[0], yv.x, biasA2);
                xA1_1 = fma2(wihA[1], yv.y, 0ull);
                xB0_1 = fma2(wihB[0], yv.x, biasB2);
                xB1_1 = fma2(wihB[1], yv.y, 0ull);
                xA0_1 = fma2(wihA[2], yw.x, xA0_1);
                xA1_1 = fma2(wihA[3], yw.y, xA1_1);
                xB0_1 = fma2(wihB[2], yw.x, xB0_1);
                xB1_1 = fma2(wihB[3], yw.y, xB1_1);
                xnext0 += 8;
                xnext1 += 8;
            }
            __syncthreads();
        }
    }

    // ---- backward direction: ONE step on x[T-1] from zero state ----
    {
        const float* xl0 = &S.xring[0][1][63 * 8];   // t=2047 -> buf 1, slot 63
        const float* xl1 = &S.xring[1][1][63 * 8];
        float zbA0 = bih_b[rA] + bhh_b[rA];
        float zbB0 = bih_b[rB] + bhh_b[rB];
        float zbA1 = zbA0, zbB1 = zbB0;
#pragma unroll
        for (int i = 0; i < INP; i++) {
            float wa = Wih_b[rA * INP + i], wb = Wih_b[rB * INP + i];
            zbA0 += wa * xl0[i];
            zbB0 += wb * xl0[i];
            zbA1 += wa * xl1[i];
            zbB1 += wb * xl1[i];
        }
        float aA0 = fmaf(0.5f, htanh(0.5f * zbA0), 0.5f);
        float aB0 = fmaf(actB_m, htanh(actB_s * zbB0), actB_b);
        float aA1 = fmaf(0.5f, htanh(0.5f * zbA1), 0.5f);
        float aB1 = fmaf(actB_m, htanh(actB_s * zbB1), actB_b);
        float oB0 = __shfl_xor_sync(0xFFFFFFFFu, aB0, 1);
        float oB1 = __shfl_xor_sync(0xFFFFFFFFu, aB1, 1);
        if (p == 0) {
            S.hb[0][u] = oB0 * htanh(aA0 * aB0);   // f*c0 == 0
            S.hb[1][u] = oB1 * htanh(aA1 * aB1);
        }
        __syncthreads();
    }

    // ---- final linear: out[b] = W_lin @ concat(h_f, h_b) + b_lin ----
    // final forward h is in S.h[batch][0] (last step writes parity-0 buffer)
    if ((w & 63) < 3) {
        int batch = w >> 6;
        int o = w & 63;
        float a = blin[o];
#pragma unroll 16
        for (int k = 0; k < 64; k++) a += Wlin[o * 128 + k] * S.h[batch][0][k];
#pragma unroll 16
        for (int k = 0; k < 64; k++) a += Wlin[o * 128 + 64 + k] * S.hb[batch][k];
        out[(b0 + batch) * 3 + o] = a;
    }
}

extern "C" void kernel_launch(void* const* d_in, const int* in_sizes, int n_in,
                              void* d_out, int out_size) {
    (void)in_sizes; (void)n_in; (void)out_size;
    bilstm_kernel<<<BATCH / 2, 128>>>(
        (const float*)d_in[0],  (const float*)d_in[1], (const float*)d_in[2],
        (const float*)d_in[3],  (const float*)d_in[4], (const float*)d_in[5],
        (const float*)d_in[6],  (const float*)d_in[7], (const float*)d_in[8],
        (const float*)d_in[9],  (const float*)d_in[10], (float*)d_out);
}

// round 12
// speedup vs baseline: 1.7685x; 1.1944x over previous
#include <cuda_runtime.h>
#include <cstdint>

#define T_SEQ 2048
#define BATCH 256
#define HID   64
#define INP   7
#define XSTEPS 64                    // steps per prefetch block
#define XBLK_FLOATS (XSTEPS * INP)   // 448 floats per block in GMEM
#define NBLK (T_SEQ / XSTEPS)        // 32

typedef unsigned long long ull;

__device__ __forceinline__ ull fma2(ull a, ull b, ull c) {
    ull d;
    asm("fma.rn.f32x2 %0, %1, %2, %3;" : "=l"(d) : "l"(a), "l"(b), "l"(c));
    return d;
}
__device__ __forceinline__ ull add2(ull a, ull b) {
    ull d;
    asm("add.rn.f32x2 %0, %1, %2;" : "=l"(d) : "l"(a), "l"(b));
    return d;
}
__device__ __forceinline__ ull pack2(float lo, float hi) {
    ull d; asm("mov.b64 %0, {%1, %2};" : "=l"(d) : "f"(lo), "f"(hi)); return d;
}
__device__ __forceinline__ float2 unpack2(ull a) {
    float2 r; asm("mov.b64 {%0, %1}, %2;" : "=f"(r.x), "=f"(r.y) : "l"(a)); return r;
}
__device__ __forceinline__ float htanh(float x) {
    float y; asm("tanh.approx.f32 %0, %1;" : "=f"(y) : "f"(x)); return y;
}
__device__ __forceinline__ void cpa4(uint32_t dst_smem, const float* src) {
    asm volatile("cp.async.ca.shared.global [%0], [%1], 4;" :: "r"(dst_smem), "l"(src));
}
__device__ __forceinline__ void cp_commit() {
    asm volatile("cp.async.commit_group;" ::: "memory");
}
__device__ __forceinline__ void cp_wait0() {
    asm volatile("cp.async.wait_group 0;" ::: "memory");
}

// grid = 128 CTAs x 256 threads; CTA runs 2 independent batch chains
// (chain = tid>>7), 4 warps each, per-chain NAMED barriers, chains staggered.
//
// KEY CHANGE vs R7 (best base): the xz tail-shadow now sits AFTER the
// per-step barrier instead of before it. B300's BAR.SYNC is DEFER_BLOCKING
// (no block at issue; block lands at the next dependent LDS) and its STS
// drain scales with in-flight stores. Shadow-before-bar delayed every warp's
// ARRIVAL by the shadow length for zero benefit; shadow-after-bar makes the
// arrival immediate after the h-store and overlaps the barrier drain/release
// with the shadow's independent ring-LDS + FMA2 work.
//
// Per chain: thread w in [0,128): p = w&1, u = w>>1, rows rA = p*64+u (i/f),
// rB = rA+128 (g/o); weights register-resident (2 x 32 f32x2). Per step:
// z = xz + W_hh·h (16 LDS.128 broadcast + 64 FMA2), unified MUFU.TANH
// activations, shfl_xor(1) gate exchange, p==0 lanes update c / store h
// (double-buffered). ONE named barrier per step. x streamed via cp.async
// double-buffered 64-step ring (8-float padded rows; rings contiguous so the
// unconditional shadow pointer walks 0->1 correctly; boundaries recompute).
//
// Backward direction = ONE LSTM step on x[T-1] from zero state (scan[0] of
// the reversed sequence), fused as an epilogue with the final linear.
struct ChainSmem {
    float h[2][64];             // double-buffered hidden state
    float hb[64];               // backward h (epilogue)
    float xring[2][XSTEPS * 8]; // padded x ring, 2 blocks (contiguous)
    float pad[8];               // absorbs block-edge shadow over-read
};

__global__ void __launch_bounds__(256, 1)
bilstm_kernel(const float* __restrict__ x,      // [B,T,I]
              const float* __restrict__ Wih_f,  // [256,7]
              const float* __restrict__ Whh_f,  // [256,64]
              const float* __restrict__ bih_f,  // [256]
              const float* __restrict__ bhh_f,  // [256]
              const float* __restrict__ Wih_b,  // [256,7]
              const float* __restrict__ Whh_b,  // unused (h0 = 0 for single bwd step)
              const float* __restrict__ bih_b,  // [256]
              const float* __restrict__ bhh_b,  // [256]
              const float* __restrict__ Wlin,   // [3,128]
              const float* __restrict__ blin,   // [3]
              float* __restrict__ out)          // [B,3]
{
    __shared__ __align__(16) ChainSmem cs[2];

    const int tid   = threadIdx.x;
    const int chain = tid >> 7;          // 0 or 1
    const int w     = tid & 127;         // within-chain thread id
    const int p     = w & 1;             // gate pair selector
    const int u     = w >> 1;            // hidden unit
    const int rA    = p * 64 + u;        // gate i (p=0) / f (p=1)
    const int rB    = rA + 128;          // gate g (p=0) / o (p=1)
    const int b     = blockIdx.x * 2 + chain;
    const int barid = 1 + chain;
    ChainSmem& S = cs[chain];

    const float* xb = x + (size_t)b * T_SEQ * INP;

    const uint32_t ring0 = (uint32_t)__cvta_generic_to_shared(&S.xring[0][0]);
    const uint32_t ring1 = (uint32_t)__cvta_generic_to_shared(&S.xring[1][0]);

    // ring fill: each thread copies 4 of the 512 padded floats per block
    const int e0 = 4 * w;

    // activation of row B: tanh for p=0 (gate g), sigmoid for p=1 (gate o)
    const float actB_s = (p == 0) ? 1.0f : 0.5f;
    const float actB_m = (p == 0) ? 1.0f : 0.5f;
    const float actB_b = (p == 0) ? 0.0f : 0.5f;

    // ---- weights into registers: 2 rows x 32 f32x2 ----
    ull wA[32], wB[32];
    {
        const ull* a  = reinterpret_cast<const ull*>(Whh_f + rA * HID);
        const ull* c2 = reinterpret_cast<const ull*>(Whh_f + rB * HID);
#pragma unroll
        for (int m = 0; m < 32; m++) wA[m] = a[m];
#pragma unroll
        for (int m = 0; m < 32; m++) wB[m] = c2[m];
    }
    ull wihA[4], wihB[4];
    {
        float t[8];
#pragma unroll
        for (int i = 0; i < INP; i++) t[i] = Wih_f[rA * INP + i];
        t[7] = 0.0f;
#pragma unroll
        for (int m = 0; m < 4; m++) wihA[m] = pack2(t[2 * m], t[2 * m + 1]);
#pragma unroll
        for (int i = 0; i < INP; i++) t[i] = Wih_f[rB * INP + i];
        t[7] = 0.0f;
#pragma unroll
        for (int m = 0; m < 4; m++) wihB[m] = pack2(t[2 * m], t[2 * m + 1]);
    }
    const ull biasA2 = pack2(bih_f[rA] + bhh_f[rA], 0.0f);
    const ull biasB2 = pack2(bih_f[rB] + bhh_f[rB], 0.0f);

    // ---- init: h=0, zero ring pads, prefetch blocks 0 and 1 ----
    if (w < 64) S.h[0][w] = 0.0f;
    {   // zero the j==7 pad slot of all 128 ring rows (2 bufs x 64 slots)
        int bufi = w >> 6, s = w & 63;
        S.xring[bufi][s * 8 + 7] = 0.0f;
        S.xring[bufi ^ 1][s * 8 + 7] = 0.0f;
    }
#pragma unroll
    for (int k = 0; k < 4; k++) {
        int e = e0 + k, s = e >> 3, j = e & 7;
        if (j < INP) cpa4(ring0 + (uint32_t)e * 4, xb + s * INP + j);
    }
    cp_commit();
#pragma unroll
    for (int k = 0; k < 4; k++) {
        int e = e0 + k, s = e >> 3, j = e & 7;
        if (j < INP) cpa4(ring1 + (uint32_t)e * 4, xb + XBLK_FLOATS + s * INP + j);
    }
    cp_commit();
    cp_wait0();
    float c = 0.0f;
    __syncthreads();

    // ---- one-time stagger: chain 1 burns ~300 cycles so the two chains run
    // anti-phase (identical per-step time preserves the offset) ----
    if (chain == 1) {
        float d = actB_b + 1.5f;
#pragma unroll
        for (int i = 0; i < 75; i++) d = fmaf(d, 0.9999999f, 1e-9f);
        asm volatile("" :: "f"(d));
    }

    // xz for t=0; xnext walks the contiguous ring (buf0 then buf1)
    ull xzA0, xzA1, xzB0, xzB1;
    const float* xnext = &S.xring[0][0];
    {
        ulonglong2 xv = *reinterpret_cast<const ulonglong2*>(xnext);
        ulonglong2 xw = *reinterpret_cast<const ulonglong2*>(xnext + 4);
        xzA0 = fma2(wihA[0], xv.x, biasA2);
        xzA1 = fma2(wihA[1], xv.y, 0ull);
        xzB0 = fma2(wihB[0], xv.x, biasB2);
        xzB1 = fma2(wihB[1], xv.y, 0ull);
        xzA0 = fma2(wihA[2], xw.x, xzA0);
        xzA1 = fma2(wihA[3], xw.y, xzA1);
        xzB0 = fma2(wihB[2], xw.x, xzB0);
        xzB1 = fma2(wihB[3], xw.y, xzB1);
        xnext += 8;
    }

    for (int blk = 0; blk < NBLK; blk++) {
        if (blk) {
            cp_wait0();   // ring block committed at the previous boundary landed
            asm volatile("bar.sync %0, 128;" :: "r"(barid) : "memory");
            int nb = blk + 1;
            if (nb < NBLK) {
                uint32_t dst = (nb & 1) ? ring1 : ring0;
                const float* src = xb + (size_t)nb * XBLK_FLOATS;
#pragma unroll
                for (int k = 0; k < 4; k++) {
                    int e = e0 + k, s = e >> 3, j = e & 7;
                    if (j < INP) cpa4(dst + (uint32_t)e * 4, src + s * INP + j);
                }
            }
            cp_commit();
            // recompute xz for the first step of THIS block (the block-edge
            // shadow may have read unlanded/garbage data) and reset the walk
            const float* xc = &S.xring[blk & 1][0];
            ulonglong2 xv = *reinterpret_cast<const ulonglong2*>(xc);
            ulonglong2 xw = *reinterpret_cast<const ulonglong2*>(xc + 4);
            xzA0 = fma2(wihA[0], xv.x, biasA2);
            xzA1 = fma2(wihA[1], xv.y, 0ull);
            xzB0 = fma2(wihB[0], xv.x, biasB2);
            xzB1 = fma2(wihB[1], xv.y, 0ull);
            xzA0 = fma2(wihA[2], xw.x, xzA0);
            xzA1 = fma2(wihA[3], xw.y, xzA1);
            xzB0 = fma2(wihB[2], xw.x, xzB0);
            xzB1 = fma2(wihB[3], xw.y, xzB1);
            xnext = xc + 8;
        }

#pragma unroll 2
        for (int i = 0; i < XSTEPS; i++) {
            const int par = i & 1;       // global parity == i&1 (blk*64 even)

            // ---- z = xz + W_hh·h (4 independent accumulator chains) ----
            ull a0 = xzA0, a1 = xzA1;
            ull b0 = xzB0, b1 = xzB1;
            const ulonglong2* h2 = reinterpret_cast<const ulonglong2*>(S.h[par]);
#pragma unroll
            for (int m = 0; m < 8; m++) {
                ulonglong2 ha  = h2[2 * m];
                ulonglong2 hbv = h2[2 * m + 1];
                a0 = fma2(wA[4 * m + 0], ha.x,  a0);
                a1 = fma2(wA[4 * m + 1], ha.y,  a1);
                b0 = fma2(wB[4 * m + 0], ha.x,  b0);
                b1 = fma2(wB[4 * m + 1], ha.y,  b1);
                a0 = fma2(wA[4 * m + 2], hbv.x, a0);
                a1 = fma2(wA[4 * m + 3], hbv.y, a1);
                b0 = fma2(wB[4 * m + 2], hbv.x, b0);
                b1 = fma2(wB[4 * m + 3], hbv.y, b1);
            }
            float2 fa = unpack2(add2(a0, a1));
            float2 fb = unpack2(add2(b0, b1));
            float zA = fa.x + fa.y;
            float zB = fb.x + fb.y;

            // ---- tail: activations, gate exchange, state update ----
            float aA = fmaf(0.5f, htanh(0.5f * zA), 0.5f);
            float aB = fmaf(actB_m, htanh(actB_s * zB), actB_b);
            float oA = __shfl_xor_sync(0xFFFFFFFFu, aA, 1);
            float oB = __shfl_xor_sync(0xFFFFFFFFu, aB, 1);
            if (p == 0) {
                c = oA * c + aA * aB;                // c = f*c + i*g
                S.h[par ^ 1][u] = oB * htanh(c);     // h = o*tanh(c)
            }

            // ---- barrier: arrive IMMEDIATELY after the h-store ----
            asm volatile("bar.sync %0, 128;" :: "r"(barid) : "memory");

            // ---- xz shadow AFTER the bar: overlaps drain/release (and, with
            // DEFER_BLOCKING, runs before the block lands at the next h-LDS).
            // Unconditional: walks buf0->buf1 contiguously; block boundaries
            // recompute whatever this reads at the edge. ----
            {
                ulonglong2 xv = *reinterpret_cast<const ulonglong2*>(xnext);
                ulonglong2 xw = *reinterpret_cast<const ulonglong2*>(xnext + 4);
                xzA0 = fma2(wihA[0], xv.x, biasA2);
                xzA1 = fma2(wihA[1], xv.y, 0ull);
                xzB0 = fma2(wihB[0], xv.x, biasB2);
                xzB1 = fma2(wihB[1], xv.y, 0ull);
                xzA0 = fma2(wihA[2], xw.x, xzA0);
                xzA1 = fma2(wihA[3], xw.y, xzA1);
                xzB0 = fma2(wihB[2], xw.x, xzB0);
                xzB1 = fma2(wihB[3], xw.y, xzB1);
                xnext += 8;
            }
        }
    }

    // ---- backward direction: ONE step on x[T-1] from zero state ----
    {
        const float* xl = &S.xring[1][63 * 8];   // t=2047 -> buf 1, slot 63
        float zbA = bih_b[rA] + bhh_b[rA];
        float zbB = bih_b[rB] + bhh_b[rB];
#pragma unroll
        for (int i = 0; i < INP; i++) {
            zbA += Wih_b[rA * INP + i] * xl[i];
            zbB += Wih_b[rB * INP + i] * xl[i];
        }
        float aA = fmaf(0.5f, htanh(0.5f * zbA), 0.5f);
        float aB = fmaf(actB_m, htanh(actB_s * zbB), actB_b);
        float oB = __shfl_xor_sync(0xFFFFFFFFu, aB, 1);   // o
        if (p == 0) {
            S.hb[u] = oB * htanh(aA * aB);       // f*c0 == 0
        }
        asm volatile("bar.sync %0, 128;" :: "r"(barid) : "memory");
    }

    // ---- final linear: out[b] = W_lin @ concat(h_f, h_b) + b_lin ----
    // final forward h is in S.h[0] (t=2047 has par=1, writes buffer 0)
    if (w < 3) {
        float a = blin[w];
#pragma unroll 16
        for (int k = 0; k < 64; k++) a += Wlin[w * 128 + k] * S.h[0][k];
#pragma unroll 16
        for (int k = 0; k < 64; k++) a += Wlin[w * 128 + 64 + k] * S.hb[k];
        out[b * 3 + w] = a;
    }
}

extern "C" void kernel_launch(void* const* d_in, const int* in_sizes, int n_in,
                              void* d_out, int out_size) {
    (void)in_sizes; (void)n_in; (void)out_size;
    bilstm_kernel<<<BATCH / 2, 256>>>(
        (const float*)d_in[0],  (const float*)d_in[1], (const float*)d_in[2],
        (const float*)d_in[3],  (const float*)d_in[4], (const float*)d_in[5],
        (const float*)d_in[6],  (const float*)d_in[7], (const float*)d_in[8],
        (const float*)d_in[9],  (const float*)d_in[10], (float*)d_out);
}